// round 15
// baseline (speedup 1.0000x reference)
#include <cuda_runtime.h>
#include <cstdint>

#define HW 4096
#define PP 441
#define NPAIR 28

typedef unsigned int u32;
typedef unsigned long long ull;

__device__ __align__(16) float g_cor[(size_t)NPAIR * PP * HW];
__device__ float g_stat[2 * PP];               // [0..440] sum, [441..881] sumsq
__device__ __align__(16) float g_w2t[PP * 64];
__device__ float g_bias[64];

__device__ __forceinline__ void cpa16(u32 dst, const void* src, bool v) {
    int sz = v ? 16 : 0;
    asm volatile("cp.async.cg.shared.global [%0], [%1], 16, %2;\n" :: "r"(dst), "l"(src), "r"(sz));
}
__device__ __forceinline__ void cpa_commit() { asm volatile("cp.async.commit_group;\n"); }
template <int N> __device__ __forceinline__ void cpa_wait() {
    asm volatile("cp.async.wait_group %0;\n" :: "n"(N));
}
__device__ __forceinline__ void fma2(ull& d, ull a, ull b) {
    asm("fma.rn.f32x2 %0, %1, %2, %0;" : "+l"(d) : "l"(a), "l"(b));
}
__device__ __forceinline__ ull dup2(float x) {
    ull d; u32 xi = __float_as_uint(x);
    asm("mov.b64 %0, {%1, %1};" : "=l"(d) : "r"(xi));
    return d;
}
__device__ __forceinline__ void unpk(float& lo, float& hi, ull v) {
    asm("mov.b64 {%0, %1}, %2;" : "=f"(lo), "=f"(hi) : "l"(v));
}
__device__ __forceinline__ int swzu(int u) { return u ^ ((u >> 3) & 1); }

#define F2CH 896
#define F1CH 512
#define F2SZ 3584
#define BUF  5632
#define NITEMS 672
#define NBLK 456

// per-c compute body for a q-group: G q-values, M f2 units, parity shift Rp.
template<int G, int M, int Rp>
__device__ __forceinline__ void corr_compute(const float* f1b, const float* f2b,
                                             int o1a, int o1b, const int* om,
                                             ull (&acc2)[6][4]) {
#pragma unroll
    for (int c = 0; c < 4; ++c) {
        ulonglong2 xa = *reinterpret_cast<const ulonglong2*>(f1b + c * F1CH + o1a);
        ulonglong2 xb = *reinterpret_cast<const ulonglong2*>(f1b + c * F1CH + o1b);
        ull a2[4] = {xa.x, xa.y, xb.x, xb.y};
#pragma unroll
        for (int m = 0; m < M; ++m) {
            ulonglong2 t = *reinterpret_cast<const ulonglong2*>(f2b + c * F2CH + om[m]);
#pragma unroll
            for (int k2 = 0; k2 < 4; ++k2) {
                const int j0 = 2 * m - k2 - Rp;
                const int j1 = 2 * m + 1 - k2 - Rp;
                if (j0 >= 0 && j0 < G) fma2(acc2[j0][k2], a2[k2], t.x);
                if (j1 >= 0 && j1 < G) fma2(acc2[j1][k2], a2[k2], t.y);
            }
        }
    }
}

// ---------------------------------------------------------------------------
// corr v7: KC=4, q-split-4. Persistent grid 456 (3 blocks/SM, 24 warps), 256
// thr, double-buffered smem 45056 B. Stage: p = s>>4, chunk c0 = (s&15)*4.
// Thread: qg = tid>>6, h = (tid>>3)&7, wg = tid&7.
// q-groups: sizes {6,5,5,5}, qbase {0,6,11,16}, unit ofs {0,3,5,8},
// parity Rp {0,0,1,0}, unit counts M {5,4,5,4}.
// ---------------------------------------------------------------------------
__global__ void __launch_bounds__(256, 3) corr_kernel(const float* __restrict__ feats) {
    extern __shared__ float sm[];
    const int tid = threadIdx.x;
    const u32 smb = (u32)__cvta_generic_to_shared(sm);

    // zero f2 border units once: 4c x 8r x 12 units x 2 buf = 768
    for (int idx = tid; idx < 768; idx += 256) {
        int bf = idx / 384, rem = idx % 384;
        int c = rem / 96, r2 = rem % 96, r = r2 / 12, k = r2 % 12;
        int u = (k < 5) ? k : k + 16;
        float4* p = reinterpret_cast<float4*>(sm + bf * BUF + c * F2CH + r * 112) + swzu(u);
        *p = make_float4(0.f, 0.f, 0.f, 0.f);
    }
    __syncthreads();

    const int qg = tid >> 6, h = (tid >> 3) & 7, wg = tid & 7;
    const int QB[4] = {0, 6, 11, 16};
    const int UO[4] = {0, 3, 5, 8};
    const int qbase = QB[qg], U = UO[qg];
    const int G = (qg == 0) ? 6 : 5;

    const int o1a = h * 64 + swzu(wg * 2) * 4;
    const int o1b = h * 64 + swzu(wg * 2 + 1) * 4;
    int om[5];
#pragma unroll
    for (int m = 0; m < 5; ++m) om[m] = h * 112 + swzu(wg * 2 + U + m) * 4;

    for (int it = blockIdx.x; it < NITEMS; it += NBLK) {
        const int n = it / 24, rem = it % 24;
        const int h0 = (rem / 3) * 8, pr0 = (rem % 3) * 7;
        const int bb = n / 7, tt = n % 7;
        const float* f1f = feats + (size_t)(bb * 8 + tt) * 64 * HW;
        const float* f2f = f1f + (size_t)64 * HW;

        auto issue = [&](int s, int bf) {
            const int p = pr0 + (s >> 4), c0 = (s & 15) * 4, dy = 2 * p - 20;
            const u32 bbase = smb + (u32)(bf * BUF) * 4u;
#pragma unroll
            for (int i = 0; i < 2; ++i) {  // f2: 512 units
                int idx = tid + i * 256;
                int c = idx >> 7, r = (idx >> 4) & 7, uu = idx & 15;
                int row = h0 + r + dy;
                bool v = (unsigned)row < 64u;
                int rc = v ? row : 0;
                cpa16(bbase + (u32)(c * F2CH + r * 112 + swzu(5 + uu) * 4) * 4u,
                      f2f + (size_t)(c0 + c) * HW + rc * 64 + uu * 4, v);
            }
#pragma unroll
            for (int i = 0; i < 2; ++i) {  // f1: 512 units
                int idx = tid + i * 256;
                int c = idx >> 7, r = (idx >> 4) & 7, uu = idx & 15;
                cpa16(bbase + (u32)(F2SZ + c * F1CH + r * 64 + swzu(uu) * 4) * 4u,
                      f1f + (size_t)(c0 + c) * HW + (h0 + r) * 64 + uu * 4, true);
            }
            cpa_commit();
        };

        const int NS = 112;
        ull acc2[6][4];
        issue(0, 0);
        issue(1, 1);

        for (int s = 0; s < NS; ++s) {
            const int bf = s & 1, ck = s & 15;
            if (s == NS - 1) cpa_wait<0>(); else cpa_wait<1>();
            __syncthreads();
            if (ck == 0) {
#pragma unroll
                for (int j = 0; j < 6; ++j)
#pragma unroll
                    for (int k2 = 0; k2 < 4; ++k2) acc2[j][k2] = 0ull;
            }
            const float* f1b = sm + bf * BUF + F2SZ;
            const float* f2b = sm + bf * BUF;

            if (qg == 0)      corr_compute<6, 5, 0>(f1b, f2b, o1a, o1b, om, acc2);
            else if (qg == 2) corr_compute<5, 5, 1>(f1b, f2b, o1a, o1b, om, acc2);
            else              corr_compute<5, 4, 0>(f1b, f2b, o1a, o1b, om, acc2);

            __syncthreads();
            if (s + 2 < NS) issue(s + 2, bf);
            if (ck == 15) {
                const int p = pr0 + (s >> 4);
                float* outp = g_cor + ((size_t)n * PP + (size_t)(p * 21 + qbase)) * HW
                              + (h0 + h) * 64 + wg * 8;
                for (int j = 0; j < G; ++j) {
                    ulonglong2 v0, v1;
                    v0.x = acc2[j][0]; v0.y = acc2[j][1];
                    v1.x = acc2[j][2]; v1.y = acc2[j][3];
                    *reinterpret_cast<ulonglong2*>(outp + (size_t)j * HW)     = v0;
                    *reinterpret_cast<ulonglong2*>(outp + (size_t)j * HW + 4) = v1;
                }
            }
        }
    }
}

// ---------------------------------------------------------------------------
__global__ void zero_stat_kernel() {
    int i = threadIdx.x;
    if (i < 2 * PP) g_stat[i] = 0.f;
}

// ---------------------------------------------------------------------------
__global__ void __launch_bounds__(256) stats_kernel() {
    const int p = blockIdx.x >> 1, half = blockIdx.x & 1;
    const int tid = threadIdx.x;
    float s = 0.f, ss = 0.f;
    for (int n = 0; n < NPAIR; ++n) {
        const float4* row =
            reinterpret_cast<const float4*>(g_cor + ((size_t)n * PP + p) * HW + half * 2048);
        for (int i = tid; i < 512; i += 256) {
            float4 v = row[i];
            s  += v.x + v.y + v.z + v.w;
            ss += v.x * v.x + v.y * v.y + v.z * v.z + v.w * v.w;
        }
    }
    __shared__ float rs[256], rss[256];
    rs[tid] = s; rss[tid] = ss;
    __syncthreads();
    for (int o = 128; o > 0; o >>= 1) {
        if (tid < o) { rs[tid] += rs[tid + o]; rss[tid] += rss[tid + o]; }
        __syncthreads();
    }
    if (tid == 0) {
        atomicAdd(&g_stat[p], rs[0]);
        atomicAdd(&g_stat[PP + p], rss[0]);
    }
}

// ---------------------------------------------------------------------------
__global__ void __launch_bounds__(256) fold_kernel(const float* __restrict__ gamma,
                                                   const float* __restrict__ beta,
                                                   const float* __restrict__ convw) {
    const int o = blockIdx.x, tid = threadIdx.x;
    const float inv = 1.f / (float)(NPAIR * HW);
    float bs = 0.f;
    for (int p = tid; p < PP; p += 256) {
        float mean = g_stat[p] * inv;
        float var  = g_stat[PP + p] * inv - mean * mean;
        float rstd = rsqrtf(var + 1e-5f);
        float sc = gamma[p] * rstd;
        float sh = beta[p] - sc * mean;
        float w  = convw[o * PP + p];
        g_w2t[p * 64 + o] = w * sc;
        bs += w * sh;
    }
    __shared__ float red[256];
    red[tid] = bs;
    __syncthreads();
    for (int ofs = 128; ofs > 0; ofs >>= 1) {
        if (tid < ofs) red[tid] += red[tid + ofs];
        __syncthreads();
    }
    if (tid == 0) g_bias[o] = red[0];
}

// ---------------------------------------------------------------------------
__global__ void __launch_bounds__(128) conv_kernel(float* __restrict__ out) {
    __shared__ float As[3][21 * 64];
    __shared__ float Bs[3][21 * 64];
    const int tid = threadIdx.x, n = blockIdx.y, px0 = blockIdx.x * 64;
    const int og = tid >> 4, pxg = tid & 15;
    const float* corn = g_cor + (size_t)n * PP * HW;
    const u32 sa = (u32)__cvta_generic_to_shared(As);
    const u32 sb = (u32)__cvta_generic_to_shared(Bs);

    auto issue = [&](int pc, int bf) {
#pragma unroll
        for (int i = 0; i < 6; ++i) {
            int idx = tid + i * 128;
            if (idx < 672) {
                int half = idx >= 336;
                int id2 = half ? idx - 336 : idx;
                int c = id2 >> 4, u = id2 & 15;
                if (!half)
                    cpa16(sa + (u32)(bf * 1344 + c * 64 + u * 4) * 4u,
                          corn + (size_t)(pc * 21 + c) * HW + px0 + u * 4, true);
                else
                    cpa16(sb + (u32)(bf * 1344 + c * 64 + u * 4) * 4u,
                          g_w2t + (pc * 21 + c) * 64 + u * 4, true);
            }
        }
        cpa_commit();
    };

    ull acc2[4][4];
#pragma unroll
    for (int s2 = 0; s2 < 4; ++s2)
#pragma unroll
        for (int r = 0; r < 4; ++r) acc2[s2][r] = 0ull;

    issue(0, 0);
    issue(1, 1);
    for (int pc = 0; pc < 21; ++pc) {
        const int bf = pc % 3;
        if (pc >= 19) cpa_wait<0>(); else cpa_wait<1>();
        __syncthreads();
        if (pc + 2 < 21) issue(pc + 2, (pc + 2) % 3);
#pragma unroll
        for (int i = 0; i < 21; ++i) {
            float4 a = *reinterpret_cast<const float4*>(&As[bf][i * 64 + pxg * 4]);
            ulonglong2 b01 = *reinterpret_cast<const ulonglong2*>(&Bs[bf][i * 64 + og * 8]);
            ulonglong2 b23 = *reinterpret_cast<const ulonglong2*>(&Bs[bf][i * 64 + og * 8 + 4]);
            ull b2[4] = {b01.x, b01.y, b23.x, b23.y};
            ull avd[4] = {dup2(a.x), dup2(a.y), dup2(a.z), dup2(a.w)};
#pragma unroll
            for (int s2 = 0; s2 < 4; ++s2)
#pragma unroll
                for (int r = 0; r < 4; ++r)
                    fma2(acc2[s2][r], avd[r], b2[s2]);
        }
    }

    const int b = n / 7, t = n % 7;
    float* outn = out + (size_t)(b * 8 + t) * 64 * HW + px0 + pxg * 4;
#pragma unroll
    for (int s2 = 0; s2 < 4; ++s2) {
        float lo[4], hi[4];
#pragma unroll
        for (int r = 0; r < 4; ++r) unpk(lo[r], hi[r], acc2[s2][r]);
        const float bo0 = g_bias[og * 8 + 2 * s2];
        const float bo1 = g_bias[og * 8 + 2 * s2 + 1];
        float4 v0 = make_float4(lo[0] + bo0, lo[1] + bo0, lo[2] + bo0, lo[3] + bo0);
        float4 v1 = make_float4(hi[0] + bo1, hi[1] + bo1, hi[2] + bo1, hi[3] + bo1);
        *reinterpret_cast<float4*>(outn + (size_t)(og * 8 + 2 * s2) * HW)     = v0;
        *reinterpret_cast<float4*>(outn + (size_t)(og * 8 + 2 * s2 + 1) * HW) = v1;
    }
}

// ---------------------------------------------------------------------------
__global__ void zero_tail_kernel(float* __restrict__ out) {
    int idx = blockIdx.x * 256 + threadIdx.x;
    if (idx < 262144) {
        int b = idx >> 16, r = idx & 65535;
        reinterpret_cast<float4*>(out)[(size_t)(b * 8 + 7) * 64 * 1024 + r] =
            make_float4(0.f, 0.f, 0.f, 0.f);
    }
}

// ---------------------------------------------------------------------------
extern "C" void kernel_launch(void* const* d_in, const int* in_sizes, int n_in,
                              void* d_out, int out_size) {
    const float* feats = (const float*)d_in[0];
    const float* gamma = (const float*)d_in[1];
    const float* beta  = (const float*)d_in[2];
    const float* convw = (const float*)d_in[3];
    float* out = (float*)d_out;

    const int corr_smem = 2 * BUF * 4;  // 45056 B
    cudaFuncSetAttribute(corr_kernel, cudaFuncAttributeMaxDynamicSharedMemorySize, corr_smem);

    // dummies keep corr as the 4th launch (the ncu capture window).
    zero_stat_kernel<<<1, 896>>>();
    zero_stat_kernel<<<1, 896>>>();
    zero_stat_kernel<<<1, 896>>>();
    corr_kernel<<<NBLK, 256, corr_smem>>>(feats);
    stats_kernel<<<882, 256>>>();
    fold_kernel<<<64, 256>>>(gamma, beta, convw);
    conv_kernel<<<dim3(64, 28), 128>>>(out);
    zero_tail_kernel<<<1024, 256>>>(out);
}

// round 16
// speedup vs baseline: 1.1584x; 1.1584x over previous
#include <cuda_runtime.h>
#include <cstdint>

#define HW 4096
#define PP 441
#define NPAIR 28

typedef unsigned int u32;
typedef unsigned long long ull;

__device__ __align__(16) float g_cor[(size_t)NPAIR * PP * HW];
__device__ float g_stat[2 * PP];               // [0..440] sum, [441..881] sumsq
__device__ __align__(16) float g_w2t[PP * 64];
__device__ float g_bias[64];

__device__ __forceinline__ void cpa16(u32 dst, const void* src, bool v) {
    int sz = v ? 16 : 0;
    asm volatile("cp.async.cg.shared.global [%0], [%1], 16, %2;\n" :: "r"(dst), "l"(src), "r"(sz));
}
__device__ __forceinline__ void cpa_commit() { asm volatile("cp.async.commit_group;\n"); }
template <int N> __device__ __forceinline__ void cpa_wait() {
    asm volatile("cp.async.wait_group %0;\n" :: "n"(N));
}
__device__ __forceinline__ void fma2(ull& d, ull a, ull b) {
    asm("fma.rn.f32x2 %0, %1, %2, %0;" : "+l"(d) : "l"(a), "l"(b));
}
__device__ __forceinline__ ull dup2(float x) {
    ull d; u32 xi = __float_as_uint(x);
    asm("mov.b64 %0, {%1, %1};" : "=l"(d) : "r"(xi));
    return d;
}
__device__ __forceinline__ void unpk(float& lo, float& hi, ull v) {
    asm("mov.b64 {%0, %1}, %2;" : "=f"(lo), "=f"(hi) : "l"(v));
}
__device__ __forceinline__ int swzu(int u) { return u ^ ((u >> 3) & 1); }

#define F2CH 896
#define F1CH 512
#define F2SZ 7168
#define BUF  11264
#define NITEMS 672
#define NBLK 304

// per-c compute body for a q-group: G q-values, M f2 units, parity shift Rp.
template<int G, int M, int Rp>
__device__ __forceinline__ void corr_compute(const float* f1b, const float* f2b,
                                             int o1a, int o1b, const int* om,
                                             ull (&acc2)[6][4]) {
#pragma unroll 2
    for (int c = 0; c < 8; ++c) {
        ulonglong2 xa = *reinterpret_cast<const ulonglong2*>(f1b + c * F1CH + o1a);
        ulonglong2 xb = *reinterpret_cast<const ulonglong2*>(f1b + c * F1CH + o1b);
        ull a2[4] = {xa.x, xa.y, xb.x, xb.y};
#pragma unroll
        for (int m = 0; m < M; ++m) {
            ulonglong2 t = *reinterpret_cast<const ulonglong2*>(f2b + c * F2CH + om[m]);
#pragma unroll
            for (int k2 = 0; k2 < 4; ++k2) {
                const int j0 = 2 * m - k2 - Rp;
                const int j1 = 2 * m + 1 - k2 - Rp;
                if (j0 >= 0 && j0 < G) fma2(acc2[j0][k2], a2[k2], t.x);
                if (j1 >= 0 && j1 < G) fma2(acc2[j1][k2], a2[k2], t.y);
            }
        }
    }
}

// ---------------------------------------------------------------------------
// corr v8: KC=8, q-split-4, persistent grid 304 (2 blocks/SM, 16 warps),
// 256 thr, 90112 B smem double buffer. SINGLE sync per stage with
// distance-1 issue: wait<0> -> sync -> issue(s+1, bf^1) -> compute(bf).
// (top-of-stage sync proves bf^1 fully consumed at stage s-1 -> safe.)
// ---------------------------------------------------------------------------
__global__ void __launch_bounds__(256) corr_kernel(const float* __restrict__ feats) {
    extern __shared__ float sm[];
    const int tid = threadIdx.x;
    const u32 smb = (u32)__cvta_generic_to_shared(sm);

    // zero f2 border units once: 8c x 8r x 12 units x 2 buf = 1536
    for (int idx = tid; idx < 1536; idx += 256) {
        int bf = idx / 768, rem = idx % 768;
        int c = rem / 96, r2 = rem % 96, r = r2 / 12, k = r2 % 12;
        int u = (k < 5) ? k : k + 16;
        float4* p = reinterpret_cast<float4*>(sm + bf * BUF + c * F2CH + r * 112) + swzu(u);
        *p = make_float4(0.f, 0.f, 0.f, 0.f);
    }
    __syncthreads();

    const int qg = tid >> 6, h = (tid >> 3) & 7, wg = tid & 7;
    const int QB[4] = {0, 6, 11, 16};
    const int UO[4] = {0, 3, 5, 8};
    const int qbase = QB[qg], U = UO[qg];
    const int G = (qg == 0) ? 6 : 5;

    const int o1a = h * 64 + swzu(wg * 2) * 4;
    const int o1b = h * 64 + swzu(wg * 2 + 1) * 4;
    int om[5];
#pragma unroll
    for (int m = 0; m < 5; ++m) om[m] = h * 112 + swzu(wg * 2 + U + m) * 4;

    for (int it = blockIdx.x; it < NITEMS; it += NBLK) {
        const int n = it / 24, rem = it % 24;
        const int h0 = (rem / 3) * 8, pr0 = (rem % 3) * 7;
        const int bb = n / 7, tt = n % 7;
        const float* f1f = feats + (size_t)(bb * 8 + tt) * 64 * HW;
        const float* f2f = f1f + (size_t)64 * HW;

        auto issue = [&](int s, int bf) {
            const int p = pr0 + (s >> 3), c0 = (s & 7) * 8, dy = 2 * p - 20;
            const u32 bbase = smb + (u32)(bf * BUF) * 4u;
#pragma unroll
            for (int i = 0; i < 4; ++i) {  // f2: 1024 units
                int idx = tid + i * 256;
                int c = idx >> 7, r = (idx >> 4) & 7, uu = idx & 15;
                int row = h0 + r + dy;
                bool v = (unsigned)row < 64u;
                int rc = v ? row : 0;
                cpa16(bbase + (u32)(c * F2CH + r * 112 + swzu(5 + uu) * 4) * 4u,
                      f2f + (size_t)(c0 + c) * HW + rc * 64 + uu * 4, v);
            }
#pragma unroll
            for (int i = 0; i < 4; ++i) {  // f1: 1024 units
                int idx = tid + i * 256;
                int c = idx >> 7, r = (idx >> 4) & 7, uu = idx & 15;
                cpa16(bbase + (u32)(F2SZ + c * F1CH + r * 64 + swzu(uu) * 4) * 4u,
                      f1f + (size_t)(c0 + c) * HW + (h0 + r) * 64 + uu * 4, true);
            }
            cpa_commit();
        };

        const int NS = 56;
        ull acc2[6][4];
        issue(0, 0);

        for (int s = 0; s < NS; ++s) {
            const int bf = s & 1, ck = s & 7;
            cpa_wait<0>();
            __syncthreads();
            if (s + 1 < NS) issue(s + 1, bf ^ 1);
            if (ck == 0) {
#pragma unroll
                for (int j = 0; j < 6; ++j)
#pragma unroll
                    for (int k2 = 0; k2 < 4; ++k2) acc2[j][k2] = 0ull;
            }
            const float* f1b = sm + bf * BUF + F2SZ;
            const float* f2b = sm + bf * BUF;

            if (qg == 0)      corr_compute<6, 5, 0>(f1b, f2b, o1a, o1b, om, acc2);
            else if (qg == 2) corr_compute<5, 5, 1>(f1b, f2b, o1a, o1b, om, acc2);
            else              corr_compute<5, 4, 0>(f1b, f2b, o1a, o1b, om, acc2);

            if (ck == 7) {
                const int p = pr0 + (s >> 3);
                float* outp = g_cor + ((size_t)n * PP + (size_t)(p * 21 + qbase)) * HW
                              + (h0 + h) * 64 + wg * 8;
                for (int j = 0; j < G; ++j) {
                    ulonglong2 v0, v1;
                    v0.x = acc2[j][0]; v0.y = acc2[j][1];
                    v1.x = acc2[j][2]; v1.y = acc2[j][3];
                    *reinterpret_cast<ulonglong2*>(outp + (size_t)j * HW)     = v0;
                    *reinterpret_cast<ulonglong2*>(outp + (size_t)j * HW + 4) = v1;
                }
            }
        }
    }
}

// ---------------------------------------------------------------------------
__global__ void zero_stat_kernel() {
    int i = threadIdx.x;
    if (i < 2 * PP) g_stat[i] = 0.f;
}

// ---------------------------------------------------------------------------
__global__ void __launch_bounds__(256) stats_kernel() {
    const int p = blockIdx.x >> 1, half = blockIdx.x & 1;
    const int tid = threadIdx.x;
    float s = 0.f, ss = 0.f;
    for (int n = 0; n < NPAIR; ++n) {
        const float4* row =
            reinterpret_cast<const float4*>(g_cor + ((size_t)n * PP + p) * HW + half * 2048);
        for (int i = tid; i < 512; i += 256) {
            float4 v = row[i];
            s  += v.x + v.y + v.z + v.w;
            ss += v.x * v.x + v.y * v.y + v.z * v.z + v.w * v.w;
        }
    }
    __shared__ float rs[256], rss[256];
    rs[tid] = s; rss[tid] = ss;
    __syncthreads();
    for (int o = 128; o > 0; o >>= 1) {
        if (tid < o) { rs[tid] += rs[tid + o]; rss[tid] += rss[tid + o]; }
        __syncthreads();
    }
    if (tid == 0) {
        atomicAdd(&g_stat[p], rs[0]);
        atomicAdd(&g_stat[PP + p], rss[0]);
    }
}

// ---------------------------------------------------------------------------
__global__ void __launch_bounds__(256) fold_kernel(const float* __restrict__ gamma,
                                                   const float* __restrict__ beta,
                                                   const float* __restrict__ convw) {
    const int o = blockIdx.x, tid = threadIdx.x;
    const float inv = 1.f / (float)(NPAIR * HW);
    float bs = 0.f;
    for (int p = tid; p < PP; p += 256) {
        float mean = g_stat[p] * inv;
        float var  = g_stat[PP + p] * inv - mean * mean;
        float rstd = rsqrtf(var + 1e-5f);
        float sc = gamma[p] * rstd;
        float sh = beta[p] - sc * mean;
        float w  = convw[o * PP + p];
        g_w2t[p * 64 + o] = w * sc;
        bs += w * sh;
    }
    __shared__ float red[256];
    red[tid] = bs;
    __syncthreads();
    for (int ofs = 128; ofs > 0; ofs >>= 1) {
        if (tid < ofs) red[tid] += red[tid + ofs];
        __syncthreads();
    }
    if (tid == 0) g_bias[o] = red[0];
}

// ---------------------------------------------------------------------------
__global__ void __launch_bounds__(128) conv_kernel(float* __restrict__ out) {
    __shared__ float As[3][21 * 64];
    __shared__ float Bs[3][21 * 64];
    const int tid = threadIdx.x, n = blockIdx.y, px0 = blockIdx.x * 64;
    const int og = tid >> 4, pxg = tid & 15;
    const float* corn = g_cor + (size_t)n * PP * HW;
    const u32 sa = (u32)__cvta_generic_to_shared(As);
    const u32 sb = (u32)__cvta_generic_to_shared(Bs);

    auto issue = [&](int pc, int bf) {
#pragma unroll
        for (int i = 0; i < 6; ++i) {
            int idx = tid + i * 128;
            if (idx < 672) {
                int half = idx >= 336;
                int id2 = half ? idx - 336 : idx;
                int c = id2 >> 4, u = id2 & 15;
                if (!half)
                    cpa16(sa + (u32)(bf * 1344 + c * 64 + u * 4) * 4u,
                          corn + (size_t)(pc * 21 + c) * HW + px0 + u * 4, true);
                else
                    cpa16(sb + (u32)(bf * 1344 + c * 64 + u * 4) * 4u,
                          g_w2t + (pc * 21 + c) * 64 + u * 4, true);
            }
        }
        cpa_commit();
    };

    ull acc2[4][4];
#pragma unroll
    for (int s2 = 0; s2 < 4; ++s2)
#pragma unroll
        for (int r = 0; r < 4; ++r) acc2[s2][r] = 0ull;

    issue(0, 0);
    issue(1, 1);
    for (int pc = 0; pc < 21; ++pc) {
        const int bf = pc % 3;
        if (pc >= 19) cpa_wait<0>(); else cpa_wait<1>();
        __syncthreads();
        if (pc + 2 < 21) issue(pc + 2, (pc + 2) % 3);
#pragma unroll
        for (int i = 0; i < 21; ++i) {
            float4 a = *reinterpret_cast<const float4*>(&As[bf][i * 64 + pxg * 4]);
            ulonglong2 b01 = *reinterpret_cast<const ulonglong2*>(&Bs[bf][i * 64 + og * 8]);
            ulonglong2 b23 = *reinterpret_cast<const ulonglong2*>(&Bs[bf][i * 64 + og * 8 + 4]);
            ull b2[4] = {b01.x, b01.y, b23.x, b23.y};
            ull avd[4] = {dup2(a.x), dup2(a.y), dup2(a.z), dup2(a.w)};
#pragma unroll
            for (int s2 = 0; s2 < 4; ++s2)
#pragma unroll
                for (int r = 0; r < 4; ++r)
                    fma2(acc2[s2][r], avd[r], b2[s2]);
        }
    }

    const int b = n / 7, t = n % 7;
    float* outn = out + (size_t)(b * 8 + t) * 64 * HW + px0 + pxg * 4;
#pragma unroll
    for (int s2 = 0; s2 < 4; ++s2) {
        float lo[4], hi[4];
#pragma unroll
        for (int r = 0; r < 4; ++r) unpk(lo[r], hi[r], acc2[s2][r]);
        const float bo0 = g_bias[og * 8 + 2 * s2];
        const float bo1 = g_bias[og * 8 + 2 * s2 + 1];
        float4 v0 = make_float4(lo[0] + bo0, lo[1] + bo0, lo[2] + bo0, lo[3] + bo0);
        float4 v1 = make_float4(hi[0] + bo1, hi[1] + bo1, hi[2] + bo1, hi[3] + bo1);
        *reinterpret_cast<float4*>(outn + (size_t)(og * 8 + 2 * s2) * HW)     = v0;
        *reinterpret_cast<float4*>(outn + (size_t)(og * 8 + 2 * s2 + 1) * HW) = v1;
    }
}

// ---------------------------------------------------------------------------
__global__ void zero_tail_kernel(float* __restrict__ out) {
    int idx = blockIdx.x * 256 + threadIdx.x;
    if (idx < 262144) {
        int b = idx >> 16, r = idx & 65535;
        reinterpret_cast<float4*>(out)[(size_t)(b * 8 + 7) * 64 * 1024 + r] =
            make_float4(0.f, 0.f, 0.f, 0.f);
    }
}

// ---------------------------------------------------------------------------
extern "C" void kernel_launch(void* const* d_in, const int* in_sizes, int n_in,
                              void* d_out, int out_size) {
    const float* feats = (const float*)d_in[0];
    const float* gamma = (const float*)d_in[1];
    const float* beta  = (const float*)d_in[2];
    const float* convw = (const float*)d_in[3];
    float* out = (float*)d_out;

    const int corr_smem = 2 * BUF * 4;  // 90112 B
    cudaFuncSetAttribute(corr_kernel, cudaFuncAttributeMaxDynamicSharedMemorySize, corr_smem);

    // dummies keep corr as the 4th launch (the ncu capture window).
    zero_stat_kernel<<<1, 896>>>();
    zero_stat_kernel<<<1, 896>>>();
    zero_stat_kernel<<<1, 896>>>();
    corr_kernel<<<NBLK, 256, corr_smem>>>(feats);
    stats_kernel<<<882, 256>>>();
    fold_kernel<<<64, 256>>>(gamma, beta, convw);
    conv_kernel<<<dim3(64, 28), 128>>>(out);
    zero_tail_kernel<<<1024, 256>>>(out);
}